// round 3
// baseline (speedup 1.0000x reference)
#include <cuda_runtime.h>
#include <cuda_bf16.h>
#include <cstdint>

// Problem constants
#define BG   64
#define NPG  2048
#define NN   (BG * NPG)      // 131072 nodes
#define EPG  32768
#define EE   (BG * EPG)      // 2097152 edges
#define DD   32
#define KK   1024            // kept per graph
#define BK   (BG * KK)       // 65536 kept total

// Output layout (flattened f32, reference return order)
#define OFF_X5     ((size_t)0)                       // BK*DD = 2097152
#define OFF_EI     ((size_t)(BK * DD))               // 2*EE  = 4194304
#define OFF_EA     (OFF_EI + (size_t)(2 * EE))       // EE
#define OFF_BATCH  (OFF_EA + (size_t)EE)             // BK
#define OFF_PERM   (OFF_BATCH + (size_t)BK)          // BK
#define OFF_SCORE  (OFF_PERM + (size_t)BK)           // BK

// Scratch (device globals -- no allocation allowed)
__device__ int   g_deg[NN];
__device__ int   g_cnt[NN];
__device__ int   g_off[NN];
__device__ int   g_adjeid[EE];       // edge ids grouped by dst (arbitrary order)
__device__ int   g_adjsrc[EE];       // src ids grouped by dst, EDGE order within dst
__device__ float g_agg[(size_t)NN * DD];
__device__ float g_score[NN];
__device__ int   g_newidx[NN];
__device__ int   g_perm[BK];

// ---------------------------------------------------------------------------
// 1) zero counters
__global__ void zero_kernel() {
    int i = blockIdx.x * blockDim.x + threadIdx.x;
    g_deg[i] = 0;
    g_cnt[i] = 0;
}

// 2) in-degree histogram (int atomics -> deterministic counts)
__global__ void deg_kernel(const int* __restrict__ ei) {
    int e = blockIdx.x * blockDim.x + threadIdx.x;   // < EE
    atomicAdd(&g_deg[__ldg(&ei[EE + e])], 1);
}

// ---------------------------------------------------------------------------
// 3) per-graph exclusive scan of degrees -> CSR offsets (graph base = g*EPG)
__global__ void scan_kernel() {
    __shared__ int s[2][NPG];
    int g = blockIdx.x, t = threadIdx.x;   // 1024 threads
    s[0][t]        = g_deg[g * NPG + t];
    s[0][t + 1024] = g_deg[g * NPG + t + 1024];
    __syncthreads();
    int cur = 0;
    for (int off = 1; off < NPG; off <<= 1) {
        int nxt = cur ^ 1;
        int i0 = t, i1 = t + 1024;
        int v0 = s[cur][i0] + (i0 >= off ? s[cur][i0 - off] : 0);
        int v1 = s[cur][i1] + (i1 >= off ? s[cur][i1 - off] : 0);
        s[nxt][i0] = v0; s[nxt][i1] = v1;
        __syncthreads();
        cur = nxt;
    }
    g_off[g * NPG + t]        = g * EPG + (t ? s[cur][t - 1] : 0);
    g_off[g * NPG + t + 1024] = g * EPG + s[cur][t + 1023];
}

// ---------------------------------------------------------------------------
// 4) place edge ids into CSR slots (arbitrary intra-node order)
__global__ void place_kernel(const int* __restrict__ ei) {
    int e = blockIdx.x * blockDim.x + threadIdx.x;   // < EE
    int d = __ldg(&ei[EE + e]);
    int pos = atomicAdd(&g_cnt[d], 1);
    g_adjeid[g_off[d] + pos] = e;
}

// ---------------------------------------------------------------------------
// 5) per-node sort by edge id (warp per node) -> src list in exact edge order
__global__ void sortadj_kernel(const int* __restrict__ ei) {
    int gt = blockIdx.x * blockDim.x + threadIdx.x;
    int n = gt >> 5;
    int lane = gt & 31;
    int off = g_off[n];
    int d = g_deg[n];
    if (d == 0) return;
    if (d <= 64) {
        int e0 = (lane      < d) ? g_adjeid[off + lane]      : INT_MAX;
        int e1 = (lane + 32 < d) ? g_adjeid[off + lane + 32] : INT_MAX;
        for (int k = 0; k < d; k++) {
            int m = min(e0, e1);
#pragma unroll
            for (int o = 16; o; o >>= 1)
                m = min(m, __shfl_xor_sync(0xffffffffu, m, o));
            if (lane == 0) g_adjsrc[off + k] = __ldg(&ei[m]);
            if (e0 == m) e0 = INT_MAX;
            else if (e1 == m) e1 = INT_MAX;
        }
    } else if (lane == 0) {
        // serial selection fallback (vanishingly rare)
        int cur = -1;
        for (int k = 0; k < d; k++) {
            int m = INT_MAX;
            for (int i = 0; i < d; i++) {
                int e = g_adjeid[off + i];
                if (e > cur && e < m) m = e;
            }
            g_adjsrc[off + k] = __ldg(&ei[m]);
            cur = m;
        }
    }
}

// ---------------------------------------------------------------------------
// 6) aggregation: warp per node, lane = feature. Sequential f32 adds in
//    edge order (matches XLA CPU sequential scatter-add). Loads prefetched
//    in batches of 8 (adds are the dependent chain; loads are independent).
__global__ void agg_kernel(const float* __restrict__ x) {
    int gt = blockIdx.x * blockDim.x + threadIdx.x;
    int n = gt >> 5;
    int lane = gt & 31;
    int off = g_off[n];
    int d = g_deg[n];
    float acc = 0.0f;
    for (int base = 0; base < d; base += 8) {
        int se = (base + lane < d && lane < 8) ? g_adjsrc[off + base + lane] : 0;
        float v[8];
#pragma unroll
        for (int j = 0; j < 8; j++) {
            int sj = __shfl_sync(0xffffffffu, se, j);
            v[j] = (base + j < d) ? __ldg(&x[(size_t)sj * DD + lane]) : 0.0f;
        }
#pragma unroll
        for (int j = 0; j < 8; j++)
            if (base + j < d) acc = __fadd_rn(acc, v[j]);
    }
    g_agg[(size_t)n * DD + lane] = acc;
}

// ---------------------------------------------------------------------------
// 7) score: warp per node. k-sequential single-accumulator FMA chains
//    (Eigen gebp order), (dotA + dotB) + bias, lane-sequential j-sum,
//    IEEE divide by f32 sqrt(32).
__global__ void score_kernel(const float* __restrict__ x,
                             const float* __restrict__ Wr1, const float* __restrict__ Wl1,
                             const float* __restrict__ b1,
                             const float* __restrict__ Wr2, const float* __restrict__ Wl2,
                             const float* __restrict__ b2) {
    __shared__ float sWr1[1024], sWl1[1024], sWr2[1024], sWl2[1024];
    __shared__ float sb1[32], sb2[32];
    int t = threadIdx.x;
    for (int i = t; i < 1024; i += 256) {
        sWr1[i] = Wr1[i]; sWl1[i] = Wl1[i];
        sWr2[i] = Wr2[i]; sWl2[i] = Wl2[i];
    }
    if (t < 32) { sb1[t] = b1[t]; sb2[t] = b2[t]; }
    __syncthreads();

    int lane = t & 31;
    int n = blockIdx.x * 8 + (t >> 5);
    float xv = x[(size_t)n * DD + lane];
    float av = g_agg[(size_t)n * DD + lane];
    float a1 = 0.f, c1 = 0.f, a2 = 0.f, c2 = 0.f;
#pragma unroll
    for (int k = 0; k < 32; k++) {
        float xk = __shfl_sync(0xffffffffu, xv, k);
        float ak = __shfl_sync(0xffffffffu, av, k);
        a1 = __fmaf_rn(xk, sWr1[k * 32 + lane], a1);
        c1 = __fmaf_rn(ak, sWl1[k * 32 + lane], c1);
        a2 = __fmaf_rn(xk, sWr2[k * 32 + lane], a2);
        c2 = __fmaf_rn(ak, sWl2[k * 32 + lane], c2);
    }
    float x2 = __fadd_rn(__fadd_rn(a1, c1), sb1[lane]);
    float y2 = __fadd_rn(__fadd_rn(a2, c2), sb2[lane]);
    float p = __fmul_rn(x2, y2);
    // lane-sequential sum j = 0..31 (reference reduce order)
    float s = __shfl_sync(0xffffffffu, p, 0);
#pragma unroll
    for (int k = 1; k < 32; k++)
        s = __fadd_rn(s, __shfl_sync(0xffffffffu, p, k));
    if (lane == 0)
        g_score[n] = __fdiv_rn(s, 5.656854249492380195e0f);  // f32 sqrt(32)
}

// ---------------------------------------------------------------------------
// 8) per-graph top-K via bitonic sort of 2048 keys (desc score, asc idx)
__global__ void topk_kernel(float* __restrict__ out) {
    __shared__ unsigned long long sk[NPG];
    int b = blockIdx.x;
    int t = threadIdx.x;     // 1024 threads
    int base = b * NPG;

    for (int i = t; i < NPG; i += 1024) {
        unsigned int bits = __float_as_uint(g_score[base + i]);
        unsigned int m = (bits & 0x80000000u) ? ~bits : (bits | 0x80000000u);
        unsigned int dm = ~m;    // descending order map
        sk[i] = ((unsigned long long)dm << 32) | (unsigned int)i;
    }
    __syncthreads();

    for (int k2 = 2; k2 <= NPG; k2 <<= 1) {
        for (int j = k2 >> 1; j >= 1; j >>= 1) {
            int i  = ((t & ~(j - 1)) << 1) | (t & (j - 1));
            int p2 = i | j;
            bool asc = ((i & k2) == 0);
            unsigned long long a = sk[i], c = sk[p2];
            if ((a > c) == asc) { sk[i] = c; sk[p2] = a; }
            __syncthreads();
        }
    }

    for (int p = t; p < NPG; p += 1024) {
        unsigned long long key = sk[p];
        int idx = (int)(key & 0xFFFFFFFFu);
        int g = base + idx;
        if (p < KK) {
            int r = b * KK + p;
            g_newidx[g] = r;
            g_perm[r]   = g;
            out[OFF_BATCH + r] = (float)b;
            out[OFF_PERM  + r] = (float)g;
            out[OFF_SCORE + r] = g_score[g];
        } else {
            g_newidx[g] = -1;
        }
    }
}

// ---------------------------------------------------------------------------
// 9) filter_adj: relabel edges, mask dropped ones.
__global__ void edge_filter_kernel(const int* __restrict__ ei,
                                   const float* __restrict__ ea,
                                   float* __restrict__ out) {
    int e = blockIdx.x * blockDim.x + threadIdx.x;  // < EE
    int ns = g_newidx[__ldg(&ei[e])];
    int nd = g_newidx[__ldg(&ei[EE + e])];
    bool v = (ns >= 0) && (nd >= 0);
    out[OFF_EI + e]      = v ? (float)ns : -1.0f;
    out[OFF_EI + EE + e] = v ? (float)nd : -1.0f;
    out[OFF_EA + e]      = v ? __ldg(&ea[e]) : 0.0f;
}

// ---------------------------------------------------------------------------
// 10) x5 = x[perm] + score[perm] * x3[perm], same order pinning as score.
__global__ void x5_kernel(const float* __restrict__ x,
                          const float* __restrict__ Wr3, const float* __restrict__ Wl3,
                          const float* __restrict__ b3,
                          float* __restrict__ out) {
    __shared__ float sWr3[1024], sWl3[1024], sb3[32];
    int t = threadIdx.x;
    for (int i = t; i < 1024; i += 256) { sWr3[i] = Wr3[i]; sWl3[i] = Wl3[i]; }
    if (t < 32) sb3[t] = b3[t];
    __syncthreads();

    int lane = t & 31;
    int i = blockIdx.x * 8 + (t >> 5);   // kept-node index < BK
    int p = g_perm[i];
    float sc = g_score[p];
    float xv = x[(size_t)p * DD + lane];
    float av = g_agg[(size_t)p * DD + lane];
    float a = 0.f, c = 0.f;
#pragma unroll
    for (int k = 0; k < 32; k++) {
        float xk = __shfl_sync(0xffffffffu, xv, k);
        float ak = __shfl_sync(0xffffffffu, av, k);
        a = __fmaf_rn(xk, sWr3[k * 32 + lane], a);
        c = __fmaf_rn(ak, sWl3[k * 32 + lane], c);
    }
    float x3 = __fadd_rn(__fadd_rn(a, c), sb3[lane]);
    out[OFF_X5 + (size_t)i * DD + lane] = __fadd_rn(xv, __fmul_rn(sc, x3));
}

// ---------------------------------------------------------------------------
extern "C" void kernel_launch(void* const* d_in, const int* in_sizes, int n_in,
                              void* d_out, int out_size) {
    const float* x    = (const float*)d_in[0];
    const int*   ei   = (const int*)  d_in[1];
    const float* ea   = (const float*)d_in[2];
    // d_in[3] = batch (unused: batch[perm] == graph id, computed directly)
    const float* Wr1 = (const float*)d_in[4];
    const float* Wl1 = (const float*)d_in[5];
    const float* b1  = (const float*)d_in[6];
    const float* Wr2 = (const float*)d_in[7];
    const float* Wl2 = (const float*)d_in[8];
    const float* b2  = (const float*)d_in[9];
    const float* Wr3 = (const float*)d_in[10];
    const float* Wl3 = (const float*)d_in[11];
    const float* b3  = (const float*)d_in[12];
    float* out = (float*)d_out;

    zero_kernel<<<NN / 256, 256>>>();
    deg_kernel<<<EE / 256, 256>>>(ei);
    scan_kernel<<<BG, 1024>>>();
    place_kernel<<<EE / 256, 256>>>(ei);
    sortadj_kernel<<<NN * 32 / 256, 256>>>(ei);
    agg_kernel<<<NN * 32 / 256, 256>>>(x);
    score_kernel<<<NN / 8, 256>>>(x, Wr1, Wl1, b1, Wr2, Wl2, b2);
    topk_kernel<<<BG, 1024>>>(out);
    edge_filter_kernel<<<EE / 256, 256>>>(ei, ea, out);
    x5_kernel<<<BK / 8, 256>>>(x, Wr3, Wl3, b3, out);
}

// round 5
// speedup vs baseline: 1.4950x; 1.4950x over previous
#include <cuda_runtime.h>
#include <cuda_bf16.h>
#include <cstdint>
#include <climits>

// Problem constants
#define BG   64
#define NPG  2048
#define NN   (BG * NPG)      // 131072 nodes
#define EPG  32768
#define EE   (BG * EPG)      // 2097152 edges
#define DD   32
#define KK   1024            // kept per graph
#define BK   (BG * KK)       // 65536 kept total

#define SPLITS 4             // blocks per graph
#define NLOC   (NPG / SPLITS)   // 512 nodes per block
#define CAP    9728          // adjacency capacity per block (mean 8192, +19 sigma)

// Output layout (flattened f32, reference return order)
#define OFF_X5     ((size_t)0)                       // BK*DD
#define OFF_EI     ((size_t)(BK * DD))               // 2*EE
#define OFF_EA     (OFF_EI + (size_t)(2 * EE))       // EE
#define OFF_BATCH  (OFF_EA + (size_t)EE)             // BK
#define OFF_PERM   (OFF_BATCH + (size_t)BK)          // BK
#define OFF_SCORE  (OFF_PERM + (size_t)BK)           // BK

// Scratch (device globals -- no allocation allowed)
__device__ float g_agg[(size_t)NN * DD];
__device__ float g_score[NN];
__device__ int   g_newidx[NN];
__device__ int   g_perm[BK];

// ---------------------------------------------------------------------------
// Fused: per-block CSR build (smem) + edge-order aggregation + score.
// Block b: graph g = b/SPLITS, node range [h*NLOC, (h+1)*NLOC) with h = b%SPLITS.
__global__ __launch_bounds__(1024) void fused_kernel(
    const float* __restrict__ x, const int* __restrict__ ei,
    const float* __restrict__ Wr1, const float* __restrict__ Wl1,
    const float* __restrict__ b1,
    const float* __restrict__ Wr2, const float* __restrict__ Wl2,
    const float* __restrict__ b2) {
    extern __shared__ int smem[];
    int*   hist = smem;                 // [NLOC] -> becomes exclusive offsets
    int*   cnt  = hist + NLOC;          // [NLOC]
    int*   sadj = cnt + NLOC;           // [CAP]  local edge ids grouped by dst
    float* sW   = (float*)(sadj + CAP); // 4 x 1024
    float* sb1  = sW + 4096;            // 32
    float* sb2  = sb1 + 32;             // 32

    int t = threadIdx.x;
    int g = blockIdx.x / SPLITS;
    int h = blockIdx.x % SPLITS;
    int nbase = h * NLOC;               // local node base within graph
    int ebase = g * EPG;                // global edge base of this graph

    if (t < NLOC) { hist[t] = 0; cnt[t] = 0; }
    for (int i = t; i < 1024; i += 1024) {
        sW[i] = Wr1[i]; sW[1024 + i] = Wl1[i];
        sW[2048 + i] = Wr2[i]; sW[3072 + i] = Wl2[i];
    }
    if (t < 32) { sb1[t] = b1[t]; sb2[t] = b2[t]; }
    __syncthreads();

    // --- 1) histogram of dst over this block's node range
    const int* dstp = ei + EE + ebase;
    for (int i = t; i < EPG; i += 1024) {
        int dl = __ldg(&dstp[i]) - g * NPG - nbase;
        if ((unsigned)dl < (unsigned)NLOC) atomicAdd(&hist[dl], 1);
    }
    __syncthreads();

    // --- 2) exclusive scan of hist[NLOC] (Hillis-Steele, scratch in sadj)
    {
        int* s0 = sadj;           // [NLOC]
        int* s1 = sadj + NLOC;    // [NLOC]
        if (t < NLOC) s0[t] = hist[t];
        __syncthreads();
        int cur = 0;
        for (int off = 1; off < NLOC; off <<= 1) {
            int* a = cur ? s1 : s0;
            int* b = cur ? s0 : s1;
            if (t < NLOC) b[t] = a[t] + (t >= off ? a[t - off] : 0);
            __syncthreads();
            cur ^= 1;
        }
        int* fin = cur ? s1 : s0;
        int excl = (t < NLOC) ? (t ? fin[t - 1] : 0) : 0;
        __syncthreads();          // done reading scratch
        if (t < NLOC) hist[t] = excl;
    }
    __syncthreads();

    // --- 3) place local edge ids (arbitrary order; sorted later)
    for (int i = t; i < EPG; i += 1024) {
        int dl = __ldg(&dstp[i]) - g * NPG - nbase;
        if ((unsigned)dl < (unsigned)NLOC) {
            int pos = atomicAdd(&cnt[dl], 1);
            sadj[hist[dl] + pos] = i;
        }
    }
    __syncthreads();

    // --- 4/5/6) per node: sort eids, aggregate in edge order, score
    int w = t >> 5, lane = t & 31;
    const int* srcp = ei + ebase;
    for (int j = 0; j < NLOC / 32; j++) {
        int nl = w * (NLOC / 32) + j;
        int off = hist[nl];
        int d = cnt[nl];
        int n = g * NPG + nbase + nl;

        float acc = 0.0f;
        if (d > 0 && d <= 32) {
            int v = (lane < d) ? sadj[off + lane] : INT_MAX;
            // 32-lane register bitonic sort (ascending)
#pragma unroll
            for (int k2 = 2; k2 <= 32; k2 <<= 1) {
#pragma unroll
                for (int jj = k2 >> 1; jj >= 1; jj >>= 1) {
                    int other = __shfl_xor_sync(0xffffffffu, v, jj);
                    bool up = ((lane & k2) == 0);
                    bool keepmin = (((lane & jj) == 0) == up);
                    v = keepmin ? min(v, other) : max(v, other);
                }
            }
            int src = (lane < d) ? __ldg(&srcp[v]) : 0;
#pragma unroll
            for (int jj = 0; jj < 32; jj++) {
                if (jj < d) {
                    int sj = __shfl_sync(0xffffffffu, src, jj);
                    acc = __fadd_rn(acc, __ldg(&x[(size_t)sj * DD + lane]));
                }
            }
        } else if (d > 32) {
            // rare generic path: sequential min-extraction from smem
            int cur = -1;
            for (int k = 0; k < d; k++) {
                int m = INT_MAX;
                for (int i = lane; i < d; i += 32) {
                    int e = sadj[off + i];
                    if (e > cur && e < m) m = e;
                }
#pragma unroll
                for (int o = 16; o; o >>= 1)
                    m = min(m, __shfl_xor_sync(0xffffffffu, m, o));
                int sj = __ldg(&srcp[m]);
                acc = __fadd_rn(acc, __ldg(&x[(size_t)sj * DD + lane]));
                cur = m;
            }
        }
        g_agg[(size_t)n * DD + lane] = acc;

        // score (exact R3 association order)
        float xv = __ldg(&x[(size_t)n * DD + lane]);
        float av = acc;
        float a1 = 0.f, c1 = 0.f, a2 = 0.f, c2 = 0.f;
#pragma unroll
        for (int k = 0; k < 32; k++) {
            float xk = __shfl_sync(0xffffffffu, xv, k);
            float ak = __shfl_sync(0xffffffffu, av, k);
            a1 = __fmaf_rn(xk, sW[k * 32 + lane], a1);
            c1 = __fmaf_rn(ak, sW[1024 + k * 32 + lane], c1);
            a2 = __fmaf_rn(xk, sW[2048 + k * 32 + lane], a2);
            c2 = __fmaf_rn(ak, sW[3072 + k * 32 + lane], c2);
        }
        float x2 = __fadd_rn(__fadd_rn(a1, c1), sb1[lane]);
        float y2 = __fadd_rn(__fadd_rn(a2, c2), sb2[lane]);
        float p = __fmul_rn(x2, y2);
        float s = __shfl_sync(0xffffffffu, p, 0);
#pragma unroll
        for (int k = 1; k < 32; k++)
            s = __fadd_rn(s, __shfl_sync(0xffffffffu, p, k));
        if (lane == 0)
            g_score[n] = __fdiv_rn(s, 5.656854249492380195e0f);  // f32 sqrt(32)
    }
}

// ---------------------------------------------------------------------------
// per-graph top-K via bitonic sort of 2048 keys (desc score, asc idx)
__global__ void topk_kernel(float* __restrict__ out) {
    __shared__ unsigned long long sk[NPG];
    int b = blockIdx.x;
    int t = threadIdx.x;     // 1024 threads
    int base = b * NPG;

    for (int i = t; i < NPG; i += 1024) {
        unsigned int bits = __float_as_uint(g_score[base + i]);
        unsigned int m = (bits & 0x80000000u) ? ~bits : (bits | 0x80000000u);
        unsigned int dm = ~m;    // descending order map
        sk[i] = ((unsigned long long)dm << 32) | (unsigned int)i;
    }
    __syncthreads();

    for (int k2 = 2; k2 <= NPG; k2 <<= 1) {
        for (int j = k2 >> 1; j >= 1; j >>= 1) {
            int i  = ((t & ~(j - 1)) << 1) | (t & (j - 1));
            int p2 = i | j;
            bool asc = ((i & k2) == 0);
            unsigned long long a = sk[i], c = sk[p2];
            if ((a > c) == asc) { sk[i] = c; sk[p2] = a; }
            __syncthreads();
        }
    }

    for (int p = t; p < NPG; p += 1024) {
        unsigned long long key = sk[p];
        int idx = (int)(key & 0xFFFFFFFFu);
        int g = base + idx;
        if (p < KK) {
            int r = b * KK + p;
            g_newidx[g] = r;
            g_perm[r]   = g;
            out[OFF_BATCH + r] = (float)b;
            out[OFF_PERM  + r] = (float)g;
            out[OFF_SCORE + r] = g_score[g];
        } else {
            g_newidx[g] = -1;
        }
    }
}

// ---------------------------------------------------------------------------
// filter_adj: 2 edges per thread, vectorized loads/stores.
__global__ void edge_filter_kernel(const int* __restrict__ ei,
                                   const float* __restrict__ ea,
                                   float* __restrict__ out) {
    int e2 = blockIdx.x * blockDim.x + threadIdx.x;  // < EE/2
    int2 sp = __ldg((const int2*)ei + e2);
    int2 dp = __ldg((const int2*)(ei + EE) + e2);
    float2 av = __ldg((const float2*)ea + e2);
    int ns0 = g_newidx[sp.x], ns1 = g_newidx[sp.y];
    int nd0 = g_newidx[dp.x], nd1 = g_newidx[dp.y];
    bool v0 = (ns0 >= 0) && (nd0 >= 0);
    bool v1 = (ns1 >= 0) && (nd1 >= 0);
    float2 so = make_float2(v0 ? (float)ns0 : -1.0f, v1 ? (float)ns1 : -1.0f);
    float2 do_ = make_float2(v0 ? (float)nd0 : -1.0f, v1 ? (float)nd1 : -1.0f);
    float2 ao = make_float2(v0 ? av.x : 0.0f, v1 ? av.y : 0.0f);
    ((float2*)(out + OFF_EI))[e2]      = so;
    ((float2*)(out + OFF_EI + EE))[e2] = do_;
    ((float2*)(out + OFF_EA))[e2]      = ao;
}

// ---------------------------------------------------------------------------
// x5 = x[perm] + score[perm] * x3[perm]
__global__ void x5_kernel(const float* __restrict__ x,
                          const float* __restrict__ Wr3, const float* __restrict__ Wl3,
                          const float* __restrict__ b3,
                          float* __restrict__ out) {
    __shared__ float sWr3[1024], sWl3[1024], sb3[32];
    int t = threadIdx.x;
    for (int i = t; i < 1024; i += 256) { sWr3[i] = Wr3[i]; sWl3[i] = Wl3[i]; }
    if (t < 32) sb3[t] = b3[t];
    __syncthreads();

    int lane = t & 31;
    int i = blockIdx.x * 8 + (t >> 5);   // kept-node index < BK
    int p = g_perm[i];
    float sc = g_score[p];
    float xv = x[(size_t)p * DD + lane];
    float av = g_agg[(size_t)p * DD + lane];
    float a = 0.f, c = 0.f;
#pragma unroll
    for (int k = 0; k < 32; k++) {
        float xk = __shfl_sync(0xffffffffu, xv, k);
        float ak = __shfl_sync(0xffffffffu, av, k);
        a = __fmaf_rn(xk, sWr3[k * 32 + lane], a);
        c = __fmaf_rn(ak, sWl3[k * 32 + lane], c);
    }
    float x3 = __fadd_rn(__fadd_rn(a, c), sb3[lane]);
    out[OFF_X5 + (size_t)i * DD + lane] = __fadd_rn(xv, __fmul_rn(sc, x3));
}

// ---------------------------------------------------------------------------
extern "C" void kernel_launch(void* const* d_in, const int* in_sizes, int n_in,
                              void* d_out, int out_size) {
    const float* x    = (const float*)d_in[0];
    const int*   ei   = (const int*)  d_in[1];
    const float* ea   = (const float*)d_in[2];
    // d_in[3] = batch (unused: batch[perm] == graph id, computed directly)
    const float* Wr1 = (const float*)d_in[4];
    const float* Wl1 = (const float*)d_in[5];
    const float* b1  = (const float*)d_in[6];
    const float* Wr2 = (const float*)d_in[7];
    const float* Wl2 = (const float*)d_in[8];
    const float* b2  = (const float*)d_in[9];
    const float* Wr3 = (const float*)d_in[10];
    const float* Wl3 = (const float*)d_in[11];
    const float* b3  = (const float*)d_in[12];
    float* out = (float*)d_out;

    const int smem_bytes = (NLOC + NLOC + CAP) * 4 + (4096 + 64) * 4;
    cudaFuncSetAttribute(fused_kernel,
                         cudaFuncAttributeMaxDynamicSharedMemorySize, smem_bytes);

    fused_kernel<<<BG * SPLITS, 1024, smem_bytes>>>(x, ei, Wr1, Wl1, b1, Wr2, Wl2, b2);
    topk_kernel<<<BG, 1024>>>(out);
    edge_filter_kernel<<<(EE / 2) / 256, 256>>>(ei, ea, out);
    x5_kernel<<<BK / 8, 256>>>(x, Wr3, Wl3, b3, out);
}